// round 1
// baseline (speedup 1.0000x reference)
#include <cuda_runtime.h>
#include <math.h>

// ---- problem constants (fixed by the dataset) ----
#define F      128
#define F3     384
#define NRBF   20
#define NATOMS 8000
#define NEDGES 160000
#define NMOLS  100
#define NCONV  3
#define CUTOFF 5.0f

#define TA 8    // atoms per block in phi/upd kernels
#define EB 64   // edges per block in msg kernel

// ---- device scratch (static; no runtime allocation allowed) ----
__device__ float g_s   [NATOMS * F];    // scalar features
__device__ float g_v   [NATOMS * F3];   // vector features, layout [a][f][d]
__device__ float g_ds  [NATOMS * F];    // message scalar accumulator
__device__ float g_dv  [NATOMS * F3];   // message vector accumulator
__device__ float g_phi [NATOMS * F3];   // per-atom message MLP output
__device__ float g_rbf [NEDGES * NRBF]; // radial basis per edge
__device__ float g_env [NEDGES];        // cosine cutoff envelope
__device__ float g_unit[NEDGES * 3];    // unit vectors per edge

__device__ __forceinline__ float silu(float x) { return x / (1.0f + __expf(-x)); }

// ---------------------------------------------------------------------------
// init: s = emb_table[z], v = 0, ds = 0, dv = 0
// ---------------------------------------------------------------------------
__global__ void k_init(const float* __restrict__ emb, const int* __restrict__ z)
{
    int a = blockIdx.x, f = threadIdx.x;
    g_s [a * F + f] = emb[z[a] * F + f];
    g_ds[a * F + f] = 0.0f;
    int b = a * F3 + f * 3;
    g_v [b] = 0.0f; g_v [b + 1] = 0.0f; g_v [b + 2] = 0.0f;
    g_dv[b] = 0.0f; g_dv[b + 1] = 0.0f; g_dv[b + 2] = 0.0f;
}

// ---------------------------------------------------------------------------
// edge geometry: d, unit, env, rbf (rbf only stored when env > 0)
// ---------------------------------------------------------------------------
__global__ void k_edges(const float* __restrict__ xyz, const int* __restrict__ nbrs, int E)
{
    int e = blockIdx.x * 256 + threadIdx.x;
    if (e >= E) return;
    int i = nbrs[2 * e], j = nbrs[2 * e + 1];
    float rx = xyz[3 * j]     - xyz[3 * i];
    float ry = xyz[3 * j + 1] - xyz[3 * i + 1];
    float rz = xyz[3 * j + 2] - xyz[3 * i + 2];
    float d  = sqrtf(rx * rx + ry * ry + rz * rz);
    float inv = 1.0f / d;
    g_unit[3 * e]     = rx * inv;
    g_unit[3 * e + 1] = ry * inv;
    g_unit[3 * e + 2] = rz * inv;
    float env = 0.0f;
    float t = d * (1.0f / CUTOFF);
    if (d <= CUTOFF) env = 0.5f * (cospif(t) + 1.0f);
    g_env[e] = env;
    if (env != 0.0f) {
        #pragma unroll
        for (int k = 0; k < NRBF; k++)
            g_rbf[e * NRBF + k] = sinpif((float)(k + 1) * t) * inv;
    }
}

// ---------------------------------------------------------------------------
// phi = silu(s @ W1 + b1) @ W2 + b2       (per atom; TA atoms per block)
// ---------------------------------------------------------------------------
__global__ void __launch_bounds__(128)
k_phi(const float* __restrict__ W1, const float* __restrict__ B1,
      const float* __restrict__ W2, const float* __restrict__ B2)
{
    int a0 = blockIdx.x * TA;
    int f  = threadIdx.x;
    __shared__ float ss[TA][F];
    __shared__ float hh[TA][F];

    #pragma unroll
    for (int t = 0; t < TA; t++) ss[t][f] = g_s[(a0 + t) * F + f];
    __syncthreads();

    float acc[TA];
    float b1v = B1[f];
    #pragma unroll
    for (int t = 0; t < TA; t++) acc[t] = b1v;
    for (int g = 0; g < F; g++) {
        float w = W1[g * F + f];
        #pragma unroll
        for (int t = 0; t < TA; t++) acc[t] += ss[t][g] * w;
    }
    #pragma unroll
    for (int t = 0; t < TA; t++) hh[t][f] = silu(acc[t]);
    __syncthreads();

    float p0[TA], p1[TA], p2[TA];
    float b0 = B2[f], b1 = B2[F + f], b2 = B2[2 * F + f];
    #pragma unroll
    for (int t = 0; t < TA; t++) { p0[t] = b0; p1[t] = b1; p2[t] = b2; }
    for (int g = 0; g < F; g++) {
        const float* w = W2 + g * F3;
        float w0 = w[f], w1 = w[F + f], w2 = w[2 * F + f];
        #pragma unroll
        for (int t = 0; t < TA; t++) {
            float h = hh[t][g];
            p0[t] += h * w0; p1[t] += h * w1; p2[t] += h * w2;
        }
    }
    #pragma unroll
    for (int t = 0; t < TA; t++) {
        int a = a0 + t;
        g_phi[a * F3 + f]         = p0[t];
        g_phi[a * F3 + F + f]     = p1[t];
        g_phi[a * F3 + 2 * F + f] = p2[t];
    }
}

// ---------------------------------------------------------------------------
// message pass: per edge, compute w_s = (rbf @ rbf_w + b) * env, gather phi[j],
// v[j], scatter-add into ds[i], dv[i].  rbf_w slice held in registers,
// amortized over EB edges.  env==0 edges contribute exactly zero -> skipped.
// ---------------------------------------------------------------------------
__global__ void __launch_bounds__(128)
k_msg(const float* __restrict__ RW, const float* __restrict__ RB,
      const int* __restrict__ nbrs, int E)
{
    int f = threadIdx.x;
    float rw0[NRBF], rw1[NRBF], rw2[NRBF];
    #pragma unroll
    for (int k = 0; k < NRBF; k++) {
        rw0[k] = RW[k * F3 + f];
        rw1[k] = RW[k * F3 + F + f];
        rw2[k] = RW[k * F3 + 2 * F + f];
    }
    float rb0 = RB[f], rb1 = RB[F + f], rb2 = RB[2 * F + f];

    int ebase = blockIdx.x * EB;
    for (int it = 0; it < EB; it++) {
        int e = ebase + it;
        if (e >= E) break;
        float env = g_env[e];
        if (env == 0.0f) continue;

        int i = nbrs[2 * e], j = nbrs[2 * e + 1];
        float w0 = rb0, w1 = rb1, w2 = rb2;
        #pragma unroll
        for (int k = 0; k < NRBF; k++) {
            float r = g_rbf[e * NRBF + k];
            w0 += r * rw0[k]; w1 += r * rw1[k]; w2 += r * rw2[k];
        }
        w0 *= env; w1 *= env; w2 *= env;

        const float* pj = g_phi + j * F3;
        float sp0 = pj[f] * w0;
        float sp1 = pj[F + f] * w1;
        float sp2 = pj[2 * F + f] * w2;

        atomicAdd(&g_ds[i * F + f], sp1);

        float ux = g_unit[3 * e], uy = g_unit[3 * e + 1], uz = g_unit[3 * e + 2];
        const float* vj  = g_v  + j * F3 + f * 3;
        float*       dvd = g_dv + i * F3 + f * 3;
        atomicAdd(dvd + 0, sp2 * ux + sp0 * vj[0]);
        atomicAdd(dvd + 1, sp2 * uy + sp0 * vj[1]);
        atomicAdd(dvd + 2, sp2 * uz + sp0 * vj[2]);
    }
}

// ---------------------------------------------------------------------------
// update: s += ds; v += dv; u_v = v@U; v_v = v@V; gated MLP; s += ds_u; v += dv_u.
// Also zeroes ds/dv for the next conv layer.  TA atoms per block.
// ---------------------------------------------------------------------------
__global__ void __launch_bounds__(128)
k_upd(const float* __restrict__ U,  const float* __restrict__ V,
      const float* __restrict__ W1, const float* __restrict__ B1,
      const float* __restrict__ W2, const float* __restrict__ B2)
{
    int a0 = blockIdx.x * TA;
    int f  = threadIdx.x;
    __shared__ float sv[TA][F * 3];   // v after message update, [t][f*3+d]
    __shared__ float st[TA][2 * F];   // stack = [s_new, |v_v|]
    __shared__ float sh[TA][F];       // hidden layer

    float snew[TA];
    #pragma unroll
    for (int t = 0; t < TA; t++) {
        int a = a0 + t;
        float s1 = g_s[a * F + f] + g_ds[a * F + f];
        g_ds[a * F + f] = 0.0f;
        snew[t]  = s1;
        st[t][f] = s1;
        #pragma unroll
        for (int d = 0; d < 3; d++) {
            float vv = g_v[a * F3 + f * 3 + d] + g_dv[a * F3 + f * 3 + d];
            g_dv[a * F3 + f * 3 + d] = 0.0f;
            sv[t][f * 3 + d] = vv;
        }
    }
    __syncthreads();

    // u_v[g,d] = sum_f v[f,d] U[f,g] ; v_v likewise (thread f = output index g)
    float u[TA][3], w[TA][3];
    #pragma unroll
    for (int t = 0; t < TA; t++)
        u[t][0]=u[t][1]=u[t][2]=w[t][0]=w[t][1]=w[t][2]=0.0f;
    for (int g = 0; g < F; g++) {
        float Ug = U[g * F + f], Vg = V[g * F + f];
        #pragma unroll
        for (int t = 0; t < TA; t++) {
            float v0 = sv[t][g * 3], v1 = sv[t][g * 3 + 1], v2 = sv[t][g * 3 + 2];
            u[t][0] += v0 * Ug; u[t][1] += v1 * Ug; u[t][2] += v2 * Ug;
            w[t][0] += v0 * Vg; w[t][1] += v1 * Vg; w[t][2] += v2 * Vg;
        }
    }
    float uw[TA];
    #pragma unroll
    for (int t = 0; t < TA; t++) {
        float n = sqrtf(w[t][0]*w[t][0] + w[t][1]*w[t][1] + w[t][2]*w[t][2] + 1e-15f);
        st[t][F + f] = n;
        uw[t] = u[t][0]*w[t][0] + u[t][1]*w[t][1] + u[t][2]*w[t][2];
    }
    __syncthreads();

    float h[TA];
    float b1v = B1[f];
    #pragma unroll
    for (int t = 0; t < TA; t++) h[t] = b1v;
    for (int r = 0; r < 2 * F; r++) {
        float wv = W1[r * F + f];
        #pragma unroll
        for (int t = 0; t < TA; t++) h[t] += st[t][r] * wv;
    }
    #pragma unroll
    for (int t = 0; t < TA; t++) sh[t][f] = silu(h[t]);
    __syncthreads();

    float a0r[TA], a1r[TA], a2r[TA];
    float b0 = B2[f], b1 = B2[F + f], b2 = B2[2 * F + f];
    #pragma unroll
    for (int t = 0; t < TA; t++) { a0r[t] = b0; a1r[t] = b1; a2r[t] = b2; }
    for (int r = 0; r < F; r++) {
        const float* wr = W2 + r * F3;
        float w0 = wr[f], w1 = wr[F + f], w2 = wr[2 * F + f];
        #pragma unroll
        for (int t = 0; t < TA; t++) {
            float hv = sh[t][r];
            a0r[t] += hv * w0; a1r[t] += hv * w1; a2r[t] += hv * w2;
        }
    }
    #pragma unroll
    for (int t = 0; t < TA; t++) {
        int a = a0 + t;
        g_s[a * F + f] = snew[t] + uw[t] * a1r[t] + a2r[t];
        g_v[a * F3 + f * 3 + 0] = sv[t][f * 3 + 0] + u[t][0] * a0r[t];
        g_v[a * F3 + f * 3 + 1] = sv[t][f * 3 + 1] + u[t][1] * a0r[t];
        g_v[a * F3 + f * 3 + 2] = sv[t][f * 3 + 2] + u[t][2] * a0r[t];
    }
}

// ---------------------------------------------------------------------------
// readout: atom_e = silu(s @ ro_w1 + b1) @ ro_w2 + b2 ; segment-sum by mol
// ---------------------------------------------------------------------------
__global__ void k_zero_out(float* out)
{
    int t = threadIdx.x;
    if (t < NMOLS) out[t] = 0.0f;
}

__global__ void k_readout(const float* __restrict__ W1, const float* __restrict__ B1,
                          const float* __restrict__ W2, const float* __restrict__ B2,
                          const int* __restrict__ mol, float* __restrict__ out)
{
    int a = blockIdx.x;
    int t = threadIdx.x; // 64 threads
    __shared__ float ss[F];
    ss[t]      = g_s[a * F + t];
    ss[64 + t] = g_s[a * F + 64 + t];
    __syncthreads();

    float acc = B1[t];
    for (int g = 0; g < F; g++) acc += ss[g] * W1[g * 64 + t];
    float c = silu(acc) * W2[t];

    #pragma unroll
    for (int o = 16; o > 0; o >>= 1) c += __shfl_down_sync(0xffffffffu, c, o);
    __shared__ float red[2];
    if ((t & 31) == 0) red[t >> 5] = c;
    __syncthreads();
    if (t == 0) atomicAdd(&out[mol[a]], red[0] + red[1] + B2[0]);
}

// ---------------------------------------------------------------------------
// launch
// ---------------------------------------------------------------------------
extern "C" void kernel_launch(void* const* d_in, const int* in_sizes, int n_in,
                              void* d_out, int out_size)
{
    const float* xyz    = (const float*)d_in[0];
    const float* emb    = (const float*)d_in[1];
    const float* msg_w1 = (const float*)d_in[2];
    const float* msg_b1 = (const float*)d_in[3];
    const float* msg_w2 = (const float*)d_in[4];
    const float* msg_b2 = (const float*)d_in[5];
    const float* rbf_w  = (const float*)d_in[6];
    const float* rbf_b  = (const float*)d_in[7];
    const float* upd_u  = (const float*)d_in[8];
    const float* upd_v  = (const float*)d_in[9];
    const float* upd_w1 = (const float*)d_in[10];
    const float* upd_b1 = (const float*)d_in[11];
    const float* upd_w2 = (const float*)d_in[12];
    const float* upd_b2 = (const float*)d_in[13];
    const float* ro_w1  = (const float*)d_in[14];
    const float* ro_b1  = (const float*)d_in[15];
    const float* ro_w2  = (const float*)d_in[16];
    const float* ro_b2  = (const float*)d_in[17];
    const int*   z      = (const int*)d_in[18];
    const int*   nbrs   = (const int*)d_in[19];
    const int*   mol    = (const int*)d_in[20];
    float*       out    = (float*)d_out;

    int E = in_sizes[19] / 2;

    k_init <<<NATOMS, 128>>>(emb, z);
    k_edges<<<(E + 255) / 256, 256>>>(xyz, nbrs, E);

    for (int c = 0; c < NCONV; c++) {
        k_phi<<<NATOMS / TA, 128>>>(msg_w1 + c * F * F,     msg_b1 + c * F,
                                    msg_w2 + c * F * F3,    msg_b2 + c * F3);
        k_msg<<<(E + EB - 1) / EB, 128>>>(rbf_w + c * NRBF * F3, rbf_b + c * F3, nbrs, E);
        k_upd<<<NATOMS / TA, 128>>>(upd_u  + c * F * F,     upd_v  + c * F * F,
                                    upd_w1 + c * 2 * F * F, upd_b1 + c * F,
                                    upd_w2 + c * F * F3,    upd_b2 + c * F3);
    }

    k_zero_out<<<1, 128>>>(out);
    k_readout <<<NATOMS, 64>>>(ro_w1, ro_b1, ro_w2, ro_b2, mol, out);
}

// round 2
// speedup vs baseline: 1.4935x; 1.4935x over previous
#include <cuda_runtime.h>
#include <math.h>

// ---- problem constants ----
#define F      128
#define F3     384
#define NRBF   20
#define NATOMS 8000
#define NEDGES 160000
#define NMOLS  100
#define NCONV  3
#define CUTOFF 5.0f

#define TA  8    // atoms per block in phi/upd kernels
#define TAM 8    // atoms per block in msg kernel
#define CAP 64   // max active edges per destination atom (mean ~10, 17-sigma safe)

// ---- device scratch (static; no runtime allocation allowed) ----
__device__ float g_s   [NATOMS * F];     // scalar features
__device__ float g_v   [NATOMS * F3];    // vector features [a][f][3]
__device__ float g_ds  [NATOMS * F];     // message scalar accumulator
__device__ float g_dv  [NATOMS * F3];    // message vector accumulator [a][f][3]
__device__ float g_phi [NATOMS * F3];    // message MLP output [a][ch][f]
__device__ float g_rbf [NEDGES * NRBF];  // env-premultiplied radial basis
__device__ float g_env [NEDGES];         // cutoff envelope
__device__ float g_unit[NEDGES * 3];     // unit vectors
__device__ int   g_cnt [NATOMS];         // CSR: active edges per destination
__device__ int   g_list[NATOMS * CAP];   // CSR: bucketed edge ids

__device__ __forceinline__ float silu(float x) { return x / (1.0f + __expf(-x)); }

// packed fp32x2 helpers (sm_103a FFMA2 — 2x scalar FFMA issue rate)
#define FFMA2(acc, a, b) asm("fma.rn.f32x2 %0, %1, %2, %0;" : "+l"(acc) : "l"(a), "l"(b))
__device__ __forceinline__ unsigned long long pk2(float x, float y) {
    unsigned long long r; asm("mov.b64 %0, {%1, %2};" : "=l"(r) : "f"(x), "f"(y)); return r;
}
__device__ __forceinline__ float2 upk2(unsigned long long v) {
    float2 o; asm("mov.b64 {%0, %1}, %2;" : "=f"(o.x), "=f"(o.y) : "l"(v)); return o;
}

// ---------------------------------------------------------------------------
// init: s = emb_table[z], v = 0, CSR counters = 0
// ---------------------------------------------------------------------------
__global__ void k_init(const float* __restrict__ emb, const int* __restrict__ z)
{
    int a = blockIdx.x, f = threadIdx.x;
    g_s[a * F + f] = emb[z[a] * F + f];
    int b = a * F3 + f * 3;
    g_v[b] = 0.0f; g_v[b + 1] = 0.0f; g_v[b + 2] = 0.0f;
    if (f == 0) g_cnt[a] = 0;
}

// ---------------------------------------------------------------------------
// edge geometry + CSR build (active edges only, bucketed by destination i)
// ---------------------------------------------------------------------------
__global__ void k_edges(const float* __restrict__ xyz, const int* __restrict__ nbrs, int E)
{
    int e = blockIdx.x * 256 + threadIdx.x;
    if (e >= E) return;
    int i = nbrs[2 * e], j = nbrs[2 * e + 1];
    float rx = xyz[3 * j]     - xyz[3 * i];
    float ry = xyz[3 * j + 1] - xyz[3 * i + 1];
    float rz = xyz[3 * j + 2] - xyz[3 * i + 2];
    float d  = sqrtf(rx * rx + ry * ry + rz * rz);
    float inv = 1.0f / d;
    float t = d * (1.0f / CUTOFF);
    if (d <= CUTOFF) {
        float env = 0.5f * (cospif(t) + 1.0f);
        g_env[e] = env;
        g_unit[3 * e]     = rx * inv;
        g_unit[3 * e + 1] = ry * inv;
        g_unit[3 * e + 2] = rz * inv;
        float s = env * inv;
        #pragma unroll
        for (int k = 0; k < NRBF; k++)
            g_rbf[e * NRBF + k] = sinpif((float)(k + 1) * t) * s;
        int pos = atomicAdd(&g_cnt[i], 1);
        if (pos < CAP) g_list[i * CAP + pos] = e;
    }
}

// ---------------------------------------------------------------------------
// phi = silu(s @ W1 + b1) @ W2 + b2   (TA atoms per block, packed f32x2)
// ---------------------------------------------------------------------------
__global__ void __launch_bounds__(128)
k_phi(const float* __restrict__ W1, const float* __restrict__ B1,
      const float* __restrict__ W2, const float* __restrict__ B2)
{
    int a0 = blockIdx.x * TA;
    int f  = threadIdx.x;
    __shared__ float ssT[F][TA];   // [g][t]
    __shared__ float hhT[F][TA];

    #pragma unroll
    for (int t = 0; t < TA; t++) ssT[f][t] = g_s[(a0 + t) * F + f];
    __syncthreads();

    unsigned long long acc[TA / 2];
    {
        unsigned long long b = pk2(B1[f], B1[f]);
        #pragma unroll
        for (int p = 0; p < TA / 2; p++) acc[p] = b;
    }
    for (int g = 0; g < F; g++) {
        float w = W1[g * F + f];
        unsigned long long ww = pk2(w, w);
        const unsigned long long* row = (const unsigned long long*)&ssT[g][0];
        #pragma unroll
        for (int p = 0; p < TA / 2; p++) FFMA2(acc[p], row[p], ww);
    }
    #pragma unroll
    for (int p = 0; p < TA / 2; p++) {
        float2 x = upk2(acc[p]);
        hhT[f][2 * p]     = silu(x.x);
        hhT[f][2 * p + 1] = silu(x.y);
    }
    __syncthreads();

    unsigned long long p0[TA / 2], p1[TA / 2], p2[TA / 2];
    {
        unsigned long long b0 = pk2(B2[f], B2[f]);
        unsigned long long b1 = pk2(B2[F + f], B2[F + f]);
        unsigned long long b2 = pk2(B2[2 * F + f], B2[2 * F + f]);
        #pragma unroll
        for (int p = 0; p < TA / 2; p++) { p0[p] = b0; p1[p] = b1; p2[p] = b2; }
    }
    for (int g = 0; g < F; g++) {
        const float* w = W2 + g * F3;
        unsigned long long w0 = pk2(w[f], w[f]);
        unsigned long long w1 = pk2(w[F + f], w[F + f]);
        unsigned long long w2 = pk2(w[2 * F + f], w[2 * F + f]);
        const unsigned long long* row = (const unsigned long long*)&hhT[g][0];
        #pragma unroll
        for (int p = 0; p < TA / 2; p++) {
            FFMA2(p0[p], row[p], w0);
            FFMA2(p1[p], row[p], w1);
            FFMA2(p2[p], row[p], w2);
        }
    }
    #pragma unroll
    for (int p = 0; p < TA / 2; p++) {
        float2 x0 = upk2(p0[p]), x1 = upk2(p1[p]), x2 = upk2(p2[p]);
        int a = a0 + 2 * p;
        g_phi[a * F3 + f]               = x0.x;
        g_phi[(a + 1) * F3 + f]         = x0.y;
        g_phi[a * F3 + F + f]           = x1.x;
        g_phi[(a + 1) * F3 + F + f]     = x1.y;
        g_phi[a * F3 + 2 * F + f]       = x2.x;
        g_phi[(a + 1) * F3 + 2 * F + f] = x2.y;
    }
}

// ---------------------------------------------------------------------------
// message pass over CSR buckets: no atomics, no inactive edges.
// rbf_w slice lives in smem (30 KB), shared by all edges of the block.
// ---------------------------------------------------------------------------
__global__ void __launch_bounds__(128)
k_msg(const float* __restrict__ RW, const float* __restrict__ RB,
      const int* __restrict__ nbrs)
{
    __shared__ float rw[NRBF * F3];
    int f = threadIdx.x;
    for (int idx = f; idx < NRBF * F3; idx += 128) rw[idx] = RW[idx];
    __syncthreads();

    float rb0 = RB[f], rb1 = RB[F + f], rb2 = RB[2 * F + f];
    int a0 = blockIdx.x * TAM;

    for (int t = 0; t < TAM; t++) {
        int a = a0 + t;
        int n = g_cnt[a];
        if (n > CAP) n = CAP;
        float ds = 0.0f, dv0 = 0.0f, dv1 = 0.0f, dv2 = 0.0f;
        for (int k = 0; k < n; k++) {
            int e = g_list[a * CAP + k];
            int j = nbrs[2 * e + 1];
            float env = g_env[e];
            float w0 = env * rb0, w1 = env * rb1, w2 = env * rb2;
            const float* re = g_rbf + e * NRBF;
            #pragma unroll
            for (int q = 0; q < NRBF; q++) {
                float r = re[q];
                w0 += r * rw[q * F3 + f];
                w1 += r * rw[q * F3 + F + f];
                w2 += r * rw[q * F3 + 2 * F + f];
            }
            const float* pj = g_phi + j * F3;
            float sp0 = pj[f] * w0;
            float sp1 = pj[F + f] * w1;
            float sp2 = pj[2 * F + f] * w2;
            ds += sp1;
            float ux = g_unit[3 * e], uy = g_unit[3 * e + 1], uz = g_unit[3 * e + 2];
            const float* vj = g_v + j * F3 + f * 3;
            dv0 += sp2 * ux + sp0 * vj[0];
            dv1 += sp2 * uy + sp0 * vj[1];
            dv2 += sp2 * uz + sp0 * vj[2];
        }
        g_ds[a * F + f] = ds;
        g_dv[a * F3 + f * 3]     = dv0;
        g_dv[a * F3 + f * 3 + 1] = dv1;
        g_dv[a * F3 + f * 3 + 2] = dv2;
    }
}

// ---------------------------------------------------------------------------
// update block (packed f32x2 throughout)
// ---------------------------------------------------------------------------
__global__ void __launch_bounds__(128)
k_upd(const float* __restrict__ U,  const float* __restrict__ V,
      const float* __restrict__ W1, const float* __restrict__ B1,
      const float* __restrict__ W2, const float* __restrict__ B2)
{
    int a0 = blockIdx.x * TA;
    int f  = threadIdx.x;
    __shared__ float svT[F][3][TA];    // [g][d][t]  12 KB
    __shared__ float stT[2 * F][TA];   // [r][t]      8 KB
    __shared__ float shT[F][TA];       // [g][t]      4 KB

    float snew[TA];
    #pragma unroll
    for (int t = 0; t < TA; t++) {
        int a = a0 + t;
        float s1 = g_s[a * F + f] + g_ds[a * F + f];
        snew[t]   = s1;
        stT[f][t] = s1;
        #pragma unroll
        for (int d = 0; d < 3; d++)
            svT[f][d][t] = g_v[a * F3 + f * 3 + d] + g_dv[a * F3 + f * 3 + d];
    }
    __syncthreads();

    // u_v[t][g=f][d], v_v[t][g=f][d]
    unsigned long long ua[3][TA / 2], wa[3][TA / 2];
    #pragma unroll
    for (int d = 0; d < 3; d++)
        #pragma unroll
        for (int p = 0; p < TA / 2; p++) { ua[d][p] = 0ULL; wa[d][p] = 0ULL; }
    for (int g = 0; g < F; g++) {
        float Ug = U[g * F + f], Vg = V[g * F + f];
        unsigned long long Up = pk2(Ug, Ug), Vp = pk2(Vg, Vg);
        #pragma unroll
        for (int d = 0; d < 3; d++) {
            const unsigned long long* row = (const unsigned long long*)&svT[g][d][0];
            #pragma unroll
            for (int p = 0; p < TA / 2; p++) {
                unsigned long long r = row[p];
                FFMA2(ua[d][p], r, Up);
                FFMA2(wa[d][p], r, Vp);
            }
        }
    }
    float u[TA][3], uw[TA];
    #pragma unroll
    for (int p = 0; p < TA / 2; p++) {
        float wv[2][3];
        #pragma unroll
        for (int d = 0; d < 3; d++) {
            float2 xu = upk2(ua[d][p]);
            float2 xw = upk2(wa[d][p]);
            u[2 * p][d] = xu.x; u[2 * p + 1][d] = xu.y;
            wv[0][d] = xw.x;    wv[1][d] = xw.y;
        }
        #pragma unroll
        for (int h = 0; h < 2; h++) {
            int t = 2 * p + h;
            float n2 = wv[h][0] * wv[h][0] + wv[h][1] * wv[h][1] + wv[h][2] * wv[h][2];
            stT[F + f][t] = sqrtf(n2 + 1e-15f);
            uw[t] = u[t][0] * wv[h][0] + u[t][1] * wv[h][1] + u[t][2] * wv[h][2];
        }
    }
    __syncthreads();

    // hidden = silu(stack @ W1 + b1)
    unsigned long long hacc[TA / 2];
    {
        unsigned long long b = pk2(B1[f], B1[f]);
        #pragma unroll
        for (int p = 0; p < TA / 2; p++) hacc[p] = b;
    }
    for (int r = 0; r < 2 * F; r++) {
        float wv = W1[r * F + f];
        unsigned long long ww = pk2(wv, wv);
        const unsigned long long* row = (const unsigned long long*)&stT[r][0];
        #pragma unroll
        for (int p = 0; p < TA / 2; p++) FFMA2(hacc[p], row[p], ww);
    }
    #pragma unroll
    for (int p = 0; p < TA / 2; p++) {
        float2 x = upk2(hacc[p]);
        shT[f][2 * p]     = silu(x.x);
        shT[f][2 * p + 1] = silu(x.y);
    }
    __syncthreads();

    // a = hidden @ W2 + b2
    unsigned long long p0[TA / 2], p1[TA / 2], p2[TA / 2];
    {
        unsigned long long b0 = pk2(B2[f], B2[f]);
        unsigned long long b1 = pk2(B2[F + f], B2[F + f]);
        unsigned long long b2 = pk2(B2[2 * F + f], B2[2 * F + f]);
        #pragma unroll
        for (int p = 0; p < TA / 2; p++) { p0[p] = b0; p1[p] = b1; p2[p] = b2; }
    }
    for (int g = 0; g < F; g++) {
        const float* wr = W2 + g * F3;
        unsigned long long w0 = pk2(wr[f], wr[f]);
        unsigned long long w1 = pk2(wr[F + f], wr[F + f]);
        unsigned long long w2 = pk2(wr[2 * F + f], wr[2 * F + f]);
        const unsigned long long* row = (const unsigned long long*)&shT[g][0];
        #pragma unroll
        for (int p = 0; p < TA / 2; p++) {
            FFMA2(p0[p], row[p], w0);
            FFMA2(p1[p], row[p], w1);
            FFMA2(p2[p], row[p], w2);
        }
    }
    #pragma unroll
    for (int p = 0; p < TA / 2; p++) {
        float2 avv = upk2(p0[p]), asv = upk2(p1[p]), ass = upk2(p2[p]);
        #pragma unroll
        for (int h = 0; h < 2; h++) {
            int t = 2 * p + h;
            int a = a0 + t;
            float a_vv = h ? avv.y : avv.x;
            float a_sv = h ? asv.y : asv.x;
            float a_ss = h ? ass.y : ass.x;
            g_s[a * F + f] = snew[t] + uw[t] * a_sv + a_ss;
            #pragma unroll
            for (int d = 0; d < 3; d++)
                g_v[a * F3 + f * 3 + d] = svT[f][d][t] + u[t][d] * a_vv;
        }
    }
}

// ---------------------------------------------------------------------------
// readout
// ---------------------------------------------------------------------------
__global__ void k_zero_out(float* out)
{
    int t = threadIdx.x;
    if (t < NMOLS) out[t] = 0.0f;
}

__global__ void k_readout(const float* __restrict__ W1, const float* __restrict__ B1,
                          const float* __restrict__ W2, const float* __restrict__ B2,
                          const int* __restrict__ mol, float* __restrict__ out)
{
    int a = blockIdx.x;
    int t = threadIdx.x; // 64 threads
    __shared__ float ss[F];
    ss[t]      = g_s[a * F + t];
    ss[64 + t] = g_s[a * F + 64 + t];
    __syncthreads();

    float acc = B1[t];
    for (int g = 0; g < F; g++) acc += ss[g] * W1[g * 64 + t];
    float c = silu(acc) * W2[t];

    #pragma unroll
    for (int o = 16; o > 0; o >>= 1) c += __shfl_down_sync(0xffffffffu, c, o);
    __shared__ float red[2];
    if ((t & 31) == 0) red[t >> 5] = c;
    __syncthreads();
    if (t == 0) atomicAdd(&out[mol[a]], red[0] + red[1] + B2[0]);
}

// ---------------------------------------------------------------------------
// launch
// ---------------------------------------------------------------------------
extern "C" void kernel_launch(void* const* d_in, const int* in_sizes, int n_in,
                              void* d_out, int out_size)
{
    const float* xyz    = (const float*)d_in[0];
    const float* emb    = (const float*)d_in[1];
    const float* msg_w1 = (const float*)d_in[2];
    const float* msg_b1 = (const float*)d_in[3];
    const float* msg_w2 = (const float*)d_in[4];
    const float* msg_b2 = (const float*)d_in[5];
    const float* rbf_w  = (const float*)d_in[6];
    const float* rbf_b  = (const float*)d_in[7];
    const float* upd_u  = (const float*)d_in[8];
    const float* upd_v  = (const float*)d_in[9];
    const float* upd_w1 = (const float*)d_in[10];
    const float* upd_b1 = (const float*)d_in[11];
    const float* upd_w2 = (const float*)d_in[12];
    const float* upd_b2 = (const float*)d_in[13];
    const float* ro_w1  = (const float*)d_in[14];
    const float* ro_b1  = (const float*)d_in[15];
    const float* ro_w2  = (const float*)d_in[16];
    const float* ro_b2  = (const float*)d_in[17];
    const int*   z      = (const int*)d_in[18];
    const int*   nbrs   = (const int*)d_in[19];
    const int*   mol    = (const int*)d_in[20];
    float*       out    = (float*)d_out;

    int E = in_sizes[19] / 2;

    k_init <<<NATOMS, 128>>>(emb, z);
    k_edges<<<(E + 255) / 256, 256>>>(xyz, nbrs, E);

    for (int c = 0; c < NCONV; c++) {
        k_phi<<<NATOMS / TA, 128>>>(msg_w1 + c * F * F,     msg_b1 + c * F,
                                    msg_w2 + c * F * F3,    msg_b2 + c * F3);
        k_msg<<<NATOMS / TAM, 128>>>(rbf_w + c * NRBF * F3, rbf_b + c * F3, nbrs);
        k_upd<<<NATOMS / TA, 128>>>(upd_u  + c * F * F,     upd_v  + c * F * F,
                                    upd_w1 + c * 2 * F * F, upd_b1 + c * F,
                                    upd_w2 + c * F * F3,    upd_b2 + c * F3);
    }

    k_zero_out<<<1, 128>>>(out);
    k_readout <<<NATOMS, 64>>>(ro_w1, ro_b1, ro_w2, ro_b2, mol, out);
}

// round 3
// speedup vs baseline: 1.6105x; 1.0783x over previous
#include <cuda_runtime.h>
#include <math.h>

// ---- problem constants ----
#define F      128
#define F3     384
#define NRBF   20
#define NATOMS 8000
#define NEDGES 160000
#define NMOLS  100
#define NCONV  3
#define CUTOFF 5.0f

#define TA  8    // atoms per half in phi/upd kernels (16 per block)
#define TAM 8    // atoms per block in msg kernel (4 per half)
#define CAP 64   // max active edges per destination atom

// ---- device scratch (static; no runtime allocation allowed) ----
__device__ float g_s   [NATOMS * F];     // scalar features
__device__ float g_v   [NATOMS * F3];    // vector features [a][f][3]
__device__ float g_ds  [NATOMS * F];     // message scalar accumulator
__device__ float g_dv  [NATOMS * F3];    // message vector accumulator [a][f][3]
__device__ float g_phi [NATOMS * F3];    // message MLP output [a][ch][f]
__device__ float g_rbf [NEDGES * NRBF];  // env-premultiplied radial basis
__device__ float g_env [NEDGES];         // cutoff envelope
__device__ float g_unit[NEDGES * 3];     // unit vectors
__device__ int   g_cnt [NATOMS];         // CSR: active edges per destination
__device__ int   g_list[NATOMS * CAP];   // CSR: bucketed edge ids

__device__ __forceinline__ float silu(float x) { return x / (1.0f + __expf(-x)); }

// packed fp32x2 helpers (sm_103a FFMA2)
#define FFMA2(acc, a, b) asm("fma.rn.f32x2 %0, %1, %2, %0;" : "+l"(acc) : "l"(a), "l"(b))
__device__ __forceinline__ unsigned long long pk2(float x, float y) {
    unsigned long long r; asm("mov.b64 %0, {%1, %2};" : "=l"(r) : "f"(x), "f"(y)); return r;
}
__device__ __forceinline__ float2 upk2(unsigned long long v) {
    float2 o; asm("mov.b64 {%0, %1}, %2;" : "=f"(o.x), "=f"(o.y) : "l"(v)); return o;
}

// ---------------------------------------------------------------------------
// init
// ---------------------------------------------------------------------------
__global__ void k_init(const float* __restrict__ emb, const int* __restrict__ z)
{
    int a = blockIdx.x, f = threadIdx.x;
    g_s[a * F + f] = emb[z[a] * F + f];
    int b = a * F3 + f * 3;
    g_v[b] = 0.0f; g_v[b + 1] = 0.0f; g_v[b + 2] = 0.0f;
    if (f == 0) g_cnt[a] = 0;
}

// ---------------------------------------------------------------------------
// edge geometry + CSR build (active edges only)
// ---------------------------------------------------------------------------
__global__ void k_edges(const float* __restrict__ xyz, const int* __restrict__ nbrs, int E)
{
    int e = blockIdx.x * 256 + threadIdx.x;
    if (e >= E) return;
    int i = nbrs[2 * e], j = nbrs[2 * e + 1];
    float rx = xyz[3 * j]     - xyz[3 * i];
    float ry = xyz[3 * j + 1] - xyz[3 * i + 1];
    float rz = xyz[3 * j + 2] - xyz[3 * i + 2];
    float d  = sqrtf(rx * rx + ry * ry + rz * rz);
    float inv = 1.0f / d;
    float t = d * (1.0f / CUTOFF);
    if (d <= CUTOFF) {
        float env = 0.5f * (cospif(t) + 1.0f);
        g_env[e] = env;
        g_unit[3 * e]     = rx * inv;
        g_unit[3 * e + 1] = ry * inv;
        g_unit[3 * e + 2] = rz * inv;
        float s = env * inv;
        #pragma unroll
        for (int k = 0; k < NRBF; k++)
            g_rbf[e * NRBF + k] = sinpif((float)(k + 1) * t) * s;
        int pos = atomicAdd(&g_cnt[i], 1);
        if (pos < CAP) g_list[i * CAP + pos] = e;
    }
}

// ---------------------------------------------------------------------------
// phi = silu(s @ W1 + b1) @ W2 + b2
// 256 threads = 2 independent halves of 128; 16 atoms per block.
// ---------------------------------------------------------------------------
__global__ void __launch_bounds__(256)
k_phi(const float* __restrict__ W1, const float* __restrict__ B1,
      const float* __restrict__ W2, const float* __restrict__ B2)
{
    int tid  = threadIdx.x;
    int half = tid >> 7;
    int f    = tid & 127;
    int a0   = blockIdx.x * (2 * TA) + half * TA;

    __shared__ float ssT[2][F][TA];
    __shared__ float hhT[2][F][TA];

    #pragma unroll
    for (int t = 0; t < TA; t++) ssT[half][f][t] = g_s[(a0 + t) * F + f];
    __syncthreads();

    unsigned long long acc[TA / 2];
    {
        unsigned long long b = pk2(B1[f], B1[f]);
        #pragma unroll
        for (int p = 0; p < TA / 2; p++) acc[p] = b;
    }
    for (int g = 0; g < F; g++) {
        float w = W1[g * F + f];
        unsigned long long ww = pk2(w, w);
        const unsigned long long* row = (const unsigned long long*)&ssT[half][g][0];
        #pragma unroll
        for (int p = 0; p < TA / 2; p++) FFMA2(acc[p], row[p], ww);
    }
    #pragma unroll
    for (int p = 0; p < TA / 2; p++) {
        float2 x = upk2(acc[p]);
        hhT[half][f][2 * p]     = silu(x.x);
        hhT[half][f][2 * p + 1] = silu(x.y);
    }
    __syncthreads();

    unsigned long long p0[TA / 2], p1[TA / 2], p2[TA / 2];
    {
        unsigned long long b0 = pk2(B2[f], B2[f]);
        unsigned long long b1 = pk2(B2[F + f], B2[F + f]);
        unsigned long long b2 = pk2(B2[2 * F + f], B2[2 * F + f]);
        #pragma unroll
        for (int p = 0; p < TA / 2; p++) { p0[p] = b0; p1[p] = b1; p2[p] = b2; }
    }
    for (int g = 0; g < F; g++) {
        const float* w = W2 + g * F3;
        unsigned long long w0 = pk2(w[f], w[f]);
        unsigned long long w1 = pk2(w[F + f], w[F + f]);
        unsigned long long w2 = pk2(w[2 * F + f], w[2 * F + f]);
        const unsigned long long* row = (const unsigned long long*)&hhT[half][g][0];
        #pragma unroll
        for (int p = 0; p < TA / 2; p++) {
            FFMA2(p0[p], row[p], w0);
            FFMA2(p1[p], row[p], w1);
            FFMA2(p2[p], row[p], w2);
        }
    }
    #pragma unroll
    for (int p = 0; p < TA / 2; p++) {
        float2 x0 = upk2(p0[p]), x1 = upk2(p1[p]), x2 = upk2(p2[p]);
        int a = a0 + 2 * p;
        g_phi[a * F3 + f]               = x0.x;
        g_phi[(a + 1) * F3 + f]         = x0.y;
        g_phi[a * F3 + F + f]           = x1.x;
        g_phi[(a + 1) * F3 + F + f]     = x1.y;
        g_phi[a * F3 + 2 * F + f]       = x2.x;
        g_phi[(a + 1) * F3 + 2 * F + f] = x2.y;
    }
}

// ---------------------------------------------------------------------------
// message pass over CSR buckets.
// 256 threads = 2 halves; each half handles 4 atoms; per atom the edge
// metadata (j, env, unit, rbf) is cooperatively preloaded into smem, then the
// edge loop software-pipelines the phi[j]/v[j] gathers against the rbf FMAs.
// ---------------------------------------------------------------------------
__global__ void __launch_bounds__(256)
k_msg(const float* __restrict__ RW, const float* __restrict__ RB,
      const int* __restrict__ nbrs)
{
    __shared__ unsigned long long rwp[NRBF * F]; // (ch0,ch1) pairs, 20 KB
    __shared__ float              rw2[NRBF * F]; // ch2, 10 KB
    __shared__ int   sj  [2][CAP];
    __shared__ float senv[2][CAP];
    __shared__ float sux [2][CAP];
    __shared__ float suy [2][CAP];
    __shared__ float suz [2][CAP];
    __shared__ float srbf[2][CAP][NRBF];

    int tid  = threadIdx.x;
    int half = tid >> 7;
    int f    = tid & 127;

    for (int idx = tid; idx < NRBF * F; idx += 256) {
        int q = idx >> 7, ff = idx & 127;
        rwp[idx] = pk2(RW[q * F3 + ff], RW[q * F3 + F + ff]);
        rw2[idx] = RW[q * F3 + 2 * F + ff];
    }
    float rb0 = RB[f], rb1 = RB[F + f], rb2 = RB[2 * F + f];

    int abase = blockIdx.x * TAM + half * (TAM / 2);

    for (int it = 0; it < TAM / 2; it++) {
        int a = abase + it;
        int n = g_cnt[a];
        if (n > CAP) n = CAP;

        __syncthreads();   // previous iteration's smem reads done (also covers weight writes)
        if (f < n) {
            int e = g_list[a * CAP + f];
            sj  [half][f] = nbrs[2 * e + 1];
            senv[half][f] = g_env[e];
            sux [half][f] = g_unit[3 * e];
            suy [half][f] = g_unit[3 * e + 1];
            suz [half][f] = g_unit[3 * e + 2];
            const float4* rp = (const float4*)(g_rbf + e * NRBF);
            float4* dst = (float4*)&srbf[half][f][0];
            #pragma unroll
            for (int x = 0; x < NRBF / 4; x++) dst[x] = rp[x];
        }
        __syncthreads();

        float ds = 0.0f, dv0 = 0.0f, dv1 = 0.0f, dv2 = 0.0f;
        float pj0 = 0.f, pj1 = 0.f, pj2 = 0.f, vj0 = 0.f, vj1 = 0.f, vj2 = 0.f;
        if (n > 0) {
            int j = sj[half][0];
            const float* pj = g_phi + j * F3;
            pj0 = pj[f]; pj1 = pj[F + f]; pj2 = pj[2 * F + f];
            const float* vj = g_v + j * F3 + f * 3;
            vj0 = vj[0]; vj1 = vj[1]; vj2 = vj[2];
        }
        for (int k = 0; k < n; k++) {
            float npj0 = 0.f, npj1 = 0.f, npj2 = 0.f, nvj0 = 0.f, nvj1 = 0.f, nvj2 = 0.f;
            if (k + 1 < n) {
                int jn = sj[half][k + 1];
                const float* pj = g_phi + jn * F3;
                npj0 = pj[f]; npj1 = pj[F + f]; npj2 = pj[2 * F + f];
                const float* vj = g_v + jn * F3 + f * 3;
                nvj0 = vj[0]; nvj1 = vj[1]; nvj2 = vj[2];
            }
            float env = senv[half][k];
            unsigned long long w01 = pk2(env * rb0, env * rb1);
            float w2v = env * rb2;
            #pragma unroll
            for (int q = 0; q < NRBF; q++) {
                float r = srbf[half][k][q];
                unsigned long long rr = pk2(r, r);
                FFMA2(w01, rr, rwp[q * F + f]);
                w2v = fmaf(r, rw2[q * F + f], w2v);
            }
            float2 wxy = upk2(w01);
            float sp0 = pj0 * wxy.x;
            float sp1 = pj1 * wxy.y;
            float sp2 = pj2 * w2v;
            ds += sp1;
            float ux = sux[half][k], uy = suy[half][k], uz = suz[half][k];
            dv0 += sp2 * ux + sp0 * vj0;
            dv1 += sp2 * uy + sp0 * vj1;
            dv2 += sp2 * uz + sp0 * vj2;
            pj0 = npj0; pj1 = npj1; pj2 = npj2;
            vj0 = nvj0; vj1 = nvj1; vj2 = nvj2;
        }
        g_ds[a * F + f] = ds;
        g_dv[a * F3 + f * 3]     = dv0;
        g_dv[a * F3 + f * 3 + 1] = dv1;
        g_dv[a * F3 + f * 3 + 2] = dv2;
    }
}

// ---------------------------------------------------------------------------
// update block (256 threads = 2 halves x 8 atoms; hidden buffer aliases the
// dead stack buffer to keep static smem at 40 KB)
// ---------------------------------------------------------------------------
__global__ void __launch_bounds__(256)
k_upd(const float* __restrict__ U,  const float* __restrict__ V,
      const float* __restrict__ W1, const float* __restrict__ B1,
      const float* __restrict__ W2, const float* __restrict__ B2)
{
    int tid  = threadIdx.x;
    int half = tid >> 7;
    int f    = tid & 127;
    int a0   = blockIdx.x * (2 * TA) + half * TA;

    __shared__ float svT[2][F][3][TA];    // 24 KB
    __shared__ float stT[2][2 * F][TA];   // 16 KB (reused as shT after W1 pass)
    float (*shT)[F][TA] = (float (*)[F][TA])&stT[0][0][0];  // overlay, 8 KB

    float snew[TA];
    #pragma unroll
    for (int t = 0; t < TA; t++) {
        int a = a0 + t;
        float s1 = g_s[a * F + f] + g_ds[a * F + f];
        snew[t]        = s1;
        stT[half][f][t] = s1;
        #pragma unroll
        for (int d = 0; d < 3; d++)
            svT[half][f][d][t] = g_v[a * F3 + f * 3 + d] + g_dv[a * F3 + f * 3 + d];
    }
    __syncthreads();

    unsigned long long ua[3][TA / 2], wa[3][TA / 2];
    #pragma unroll
    for (int d = 0; d < 3; d++)
        #pragma unroll
        for (int p = 0; p < TA / 2; p++) { ua[d][p] = 0ULL; wa[d][p] = 0ULL; }
    for (int g = 0; g < F; g++) {
        float Ug = U[g * F + f], Vg = V[g * F + f];
        unsigned long long Up = pk2(Ug, Ug), Vp = pk2(Vg, Vg);
        #pragma unroll
        for (int d = 0; d < 3; d++) {
            const unsigned long long* row = (const unsigned long long*)&svT[half][g][d][0];
            #pragma unroll
            for (int p = 0; p < TA / 2; p++) {
                unsigned long long r = row[p];
                FFMA2(ua[d][p], r, Up);
                FFMA2(wa[d][p], r, Vp);
            }
        }
    }
    float u[TA][3], uw[TA];
    #pragma unroll
    for (int p = 0; p < TA / 2; p++) {
        float wv[2][3];
        #pragma unroll
        for (int d = 0; d < 3; d++) {
            float2 xu = upk2(ua[d][p]);
            float2 xw = upk2(wa[d][p]);
            u[2 * p][d] = xu.x; u[2 * p + 1][d] = xu.y;
            wv[0][d] = xw.x;    wv[1][d] = xw.y;
        }
        #pragma unroll
        for (int h = 0; h < 2; h++) {
            int t = 2 * p + h;
            float n2 = wv[h][0] * wv[h][0] + wv[h][1] * wv[h][1] + wv[h][2] * wv[h][2];
            stT[half][F + f][t] = sqrtf(n2 + 1e-15f);
            uw[t] = u[t][0] * wv[h][0] + u[t][1] * wv[h][1] + u[t][2] * wv[h][2];
        }
    }
    __syncthreads();

    // hidden = silu(stack @ W1 + b1)
    unsigned long long hacc[TA / 2];
    {
        unsigned long long b = pk2(B1[f], B1[f]);
        #pragma unroll
        for (int p = 0; p < TA / 2; p++) hacc[p] = b;
    }
    for (int r = 0; r < 2 * F; r++) {
        float wv = W1[r * F + f];
        unsigned long long ww = pk2(wv, wv);
        const unsigned long long* row = (const unsigned long long*)&stT[half][r][0];
        #pragma unroll
        for (int p = 0; p < TA / 2; p++) FFMA2(hacc[p], row[p], ww);
    }
    __syncthreads();   // all stT reads complete before aliased shT writes
    #pragma unroll
    for (int p = 0; p < TA / 2; p++) {
        float2 x = upk2(hacc[p]);
        shT[half][f][2 * p]     = silu(x.x);
        shT[half][f][2 * p + 1] = silu(x.y);
    }
    __syncthreads();

    unsigned long long p0[TA / 2], p1[TA / 2], p2[TA / 2];
    {
        unsigned long long b0 = pk2(B2[f], B2[f]);
        unsigned long long b1 = pk2(B2[F + f], B2[F + f]);
        unsigned long long b2 = pk2(B2[2 * F + f], B2[2 * F + f]);
        #pragma unroll
        for (int p = 0; p < TA / 2; p++) { p0[p] = b0; p1[p] = b1; p2[p] = b2; }
    }
    for (int g = 0; g < F; g++) {
        const float* wr = W2 + g * F3;
        unsigned long long w0 = pk2(wr[f], wr[f]);
        unsigned long long w1 = pk2(wr[F + f], wr[F + f]);
        unsigned long long w2 = pk2(wr[2 * F + f], wr[2 * F + f]);
        const unsigned long long* row = (const unsigned long long*)&shT[half][g][0];
        #pragma unroll
        for (int p = 0; p < TA / 2; p++) {
            FFMA2(p0[p], row[p], w0);
            FFMA2(p1[p], row[p], w1);
            FFMA2(p2[p], row[p], w2);
        }
    }
    #pragma unroll
    for (int p = 0; p < TA / 2; p++) {
        float2 avv = upk2(p0[p]), asv = upk2(p1[p]), ass = upk2(p2[p]);
        #pragma unroll
        for (int h = 0; h < 2; h++) {
            int t = 2 * p + h;
            int a = a0 + t;
            float a_vv = h ? avv.y : avv.x;
            float a_sv = h ? asv.y : asv.x;
            float a_ss = h ? ass.y : ass.x;
            g_s[a * F + f] = snew[t] + uw[t] * a_sv + a_ss;
            #pragma unroll
            for (int d = 0; d < 3; d++)
                g_v[a * F3 + f * 3 + d] = svT[half][f][d][t] + u[t][d] * a_vv;
        }
    }
}

// ---------------------------------------------------------------------------
// readout
// ---------------------------------------------------------------------------
__global__ void k_zero_out(float* out)
{
    int t = threadIdx.x;
    if (t < NMOLS) out[t] = 0.0f;
}

__global__ void k_readout(const float* __restrict__ W1, const float* __restrict__ B1,
                          const float* __restrict__ W2, const float* __restrict__ B2,
                          const int* __restrict__ mol, float* __restrict__ out)
{
    int a = blockIdx.x;
    int t = threadIdx.x; // 64 threads
    __shared__ float ss[F];
    ss[t]      = g_s[a * F + t];
    ss[64 + t] = g_s[a * F + 64 + t];
    __syncthreads();

    float acc = B1[t];
    for (int g = 0; g < F; g++) acc += ss[g] * W1[g * 64 + t];
    float c = silu(acc) * W2[t];

    #pragma unroll
    for (int o = 16; o > 0; o >>= 1) c += __shfl_down_sync(0xffffffffu, c, o);
    __shared__ float red[2];
    if ((t & 31) == 0) red[t >> 5] = c;
    __syncthreads();
    if (t == 0) atomicAdd(&out[mol[a]], red[0] + red[1] + B2[0]);
}

// ---------------------------------------------------------------------------
// launch
// ---------------------------------------------------------------------------
extern "C" void kernel_launch(void* const* d_in, const int* in_sizes, int n_in,
                              void* d_out, int out_size)
{
    const float* xyz    = (const float*)d_in[0];
    const float* emb    = (const float*)d_in[1];
    const float* msg_w1 = (const float*)d_in[2];
    const float* msg_b1 = (const float*)d_in[3];
    const float* msg_w2 = (const float*)d_in[4];
    const float* msg_b2 = (const float*)d_in[5];
    const float* rbf_w  = (const float*)d_in[6];
    const float* rbf_b  = (const float*)d_in[7];
    const float* upd_u  = (const float*)d_in[8];
    const float* upd_v  = (const float*)d_in[9];
    const float* upd_w1 = (const float*)d_in[10];
    const float* upd_b1 = (const float*)d_in[11];
    const float* upd_w2 = (const float*)d_in[12];
    const float* upd_b2 = (const float*)d_in[13];
    const float* ro_w1  = (const float*)d_in[14];
    const float* ro_b1  = (const float*)d_in[15];
    const float* ro_w2  = (const float*)d_in[16];
    const float* ro_b2  = (const float*)d_in[17];
    const int*   z      = (const int*)d_in[18];
    const int*   nbrs   = (const int*)d_in[19];
    const int*   mol    = (const int*)d_in[20];
    float*       out    = (float*)d_out;

    int E = in_sizes[19] / 2;

    k_init <<<NATOMS, 128>>>(emb, z);
    k_edges<<<(E + 255) / 256, 256>>>(xyz, nbrs, E);

    for (int c = 0; c < NCONV; c++) {
        k_phi<<<NATOMS / (2 * TA), 256>>>(msg_w1 + c * F * F,     msg_b1 + c * F,
                                          msg_w2 + c * F * F3,    msg_b2 + c * F3);
        k_msg<<<NATOMS / TAM, 256>>>(rbf_w + c * NRBF * F3, rbf_b + c * F3, nbrs);
        k_upd<<<NATOMS / (2 * TA), 256>>>(upd_u  + c * F * F,     upd_v  + c * F * F,
                                          upd_w1 + c * 2 * F * F, upd_b1 + c * F,
                                          upd_w2 + c * F * F3,    upd_b2 + c * F3);
    }

    k_zero_out<<<1, 128>>>(out);
    k_readout <<<NATOMS, 64>>>(ro_w1, ro_b1, ro_w2, ro_b2, mol, out);
}

// round 4
// speedup vs baseline: 1.7805x; 1.1056x over previous
#include <cuda_runtime.h>
#include <math.h>

// ---- problem constants ----
#define F      128
#define F3     384
#define NRBF   20
#define NATOMS 8000
#define NEDGES 160000
#define NMOLS  100
#define NCONV  3
#define CUTOFF 5.0f

#define TA  8    // atoms per half in phi/upd kernels (16 per block)
#define TAM 4    // atoms per block in msg kernel
#define CAP 64   // max active edges per destination atom

// ---- device scratch ----
__device__ float g_s   [NATOMS * F];
__device__ float g_v   [NATOMS * F3];
__device__ float g_ds  [NATOMS * F];
__device__ float g_dv  [NATOMS * F3];
__device__ float g_phi [NATOMS * F3];
__device__ float g_rbf [NEDGES * NRBF];
__device__ float g_env [NEDGES];
__device__ float g_unit[NEDGES * 3];
__device__ int   g_cnt [NATOMS];
__device__ int   g_list[NATOMS * CAP];

__device__ __forceinline__ float silu(float x) { return x / (1.0f + __expf(-x)); }

// packed fp32x2 helpers (sm_103a FFMA2)
#define FFMA2(acc, a, b) asm("fma.rn.f32x2 %0, %1, %2, %0;" : "+l"(acc) : "l"(a), "l"(b))
__device__ __forceinline__ unsigned long long pk2(float x, float y) {
    unsigned long long r; asm("mov.b64 %0, {%1, %2};" : "=l"(r) : "f"(x), "f"(y)); return r;
}
__device__ __forceinline__ float2 upk2(unsigned long long v) {
    float2 o; asm("mov.b64 {%0, %1}, %2;" : "=f"(o.x), "=f"(o.y) : "l"(v)); return o;
}

// ---------------------------------------------------------------------------
// init
// ---------------------------------------------------------------------------
__global__ void k_init(const float* __restrict__ emb, const int* __restrict__ z)
{
    int a = blockIdx.x, f = threadIdx.x;
    g_s[a * F + f] = emb[z[a] * F + f];
    int b = a * F3 + f * 3;
    g_v[b] = 0.0f; g_v[b + 1] = 0.0f; g_v[b + 2] = 0.0f;
    if (f == 0) g_cnt[a] = 0;
}

// ---------------------------------------------------------------------------
// edge geometry + CSR build (active edges only)
// ---------------------------------------------------------------------------
__global__ void k_edges(const float* __restrict__ xyz, const int* __restrict__ nbrs, int E)
{
    int e = blockIdx.x * 256 + threadIdx.x;
    if (e >= E) return;
    int i = nbrs[2 * e], j = nbrs[2 * e + 1];
    float rx = xyz[3 * j]     - xyz[3 * i];
    float ry = xyz[3 * j + 1] - xyz[3 * i + 1];
    float rz = xyz[3 * j + 2] - xyz[3 * i + 2];
    float d  = sqrtf(rx * rx + ry * ry + rz * rz);
    float inv = 1.0f / d;
    float t = d * (1.0f / CUTOFF);
    if (d <= CUTOFF) {
        float env = 0.5f * (cospif(t) + 1.0f);
        g_env[e] = env;
        g_unit[3 * e]     = rx * inv;
        g_unit[3 * e + 1] = ry * inv;
        g_unit[3 * e + 2] = rz * inv;
        float s = env * inv;
        #pragma unroll
        for (int k = 0; k < NRBF; k++)
            g_rbf[e * NRBF + k] = sinpif((float)(k + 1) * t) * s;
        int pos = atomicAdd(&g_cnt[i], 1);
        if (pos < CAP) g_list[i * CAP + pos] = e;
    }
}

// ---------------------------------------------------------------------------
// phi = silu(s @ W1 + b1) @ W2 + b2   (256 threads = 2 halves, 16 atoms/block)
// ---------------------------------------------------------------------------
__global__ void __launch_bounds__(256)
k_phi(const float* __restrict__ W1, const float* __restrict__ B1,
      const float* __restrict__ W2, const float* __restrict__ B2)
{
    int tid  = threadIdx.x;
    int half = tid >> 7;
    int f    = tid & 127;
    int a0   = blockIdx.x * (2 * TA) + half * TA;

    __shared__ float ssT[2][F][TA];
    __shared__ float hhT[2][F][TA];

    #pragma unroll
    for (int t = 0; t < TA; t++) ssT[half][f][t] = g_s[(a0 + t) * F + f];
    __syncthreads();

    unsigned long long acc[TA / 2];
    {
        unsigned long long b = pk2(B1[f], B1[f]);
        #pragma unroll
        for (int p = 0; p < TA / 2; p++) acc[p] = b;
    }
    for (int g = 0; g < F; g++) {
        float w = W1[g * F + f];
        unsigned long long ww = pk2(w, w);
        const unsigned long long* row = (const unsigned long long*)&ssT[half][g][0];
        #pragma unroll
        for (int p = 0; p < TA / 2; p++) FFMA2(acc[p], row[p], ww);
    }
    #pragma unroll
    for (int p = 0; p < TA / 2; p++) {
        float2 x = upk2(acc[p]);
        hhT[half][f][2 * p]     = silu(x.x);
        hhT[half][f][2 * p + 1] = silu(x.y);
    }
    __syncthreads();

    unsigned long long p0[TA / 2], p1[TA / 2], p2[TA / 2];
    {
        unsigned long long b0 = pk2(B2[f], B2[f]);
        unsigned long long b1 = pk2(B2[F + f], B2[F + f]);
        unsigned long long b2 = pk2(B2[2 * F + f], B2[2 * F + f]);
        #pragma unroll
        for (int p = 0; p < TA / 2; p++) { p0[p] = b0; p1[p] = b1; p2[p] = b2; }
    }
    for (int g = 0; g < F; g++) {
        const float* w = W2 + g * F3;
        unsigned long long w0 = pk2(w[f], w[f]);
        unsigned long long w1 = pk2(w[F + f], w[F + f]);
        unsigned long long w2 = pk2(w[2 * F + f], w[2 * F + f]);
        const unsigned long long* row = (const unsigned long long*)&hhT[half][g][0];
        #pragma unroll
        for (int p = 0; p < TA / 2; p++) {
            FFMA2(p0[p], row[p], w0);
            FFMA2(p1[p], row[p], w1);
            FFMA2(p2[p], row[p], w2);
        }
    }
    #pragma unroll
    for (int p = 0; p < TA / 2; p++) {
        float2 x0 = upk2(p0[p]), x1 = upk2(p1[p]), x2 = upk2(p2[p]);
        int a = a0 + 2 * p;
        g_phi[a * F3 + f]               = x0.x;
        g_phi[(a + 1) * F3 + f]         = x0.y;
        g_phi[a * F3 + F + f]           = x1.x;
        g_phi[(a + 1) * F3 + F + f]     = x1.y;
        g_phi[a * F3 + 2 * F + f]       = x2.x;
        g_phi[(a + 1) * F3 + 2 * F + f] = x2.y;
    }
}

// ---------------------------------------------------------------------------
// message pass over CSR buckets.
// 128 threads, TAM=4 atoms serial per block.  ch0/ch1 rbf weights live in
// registers as packed pairs; ch2 weights in smem.  rbf MLP accumulation split
// into 4 chains (even/odd q x {ch01, ch2}) to halve dependent-chain depth.
// phi[j]/v[j] gathers software-pipelined one edge ahead.
// ---------------------------------------------------------------------------
__global__ void __launch_bounds__(128)
k_msg(const float* __restrict__ RW, const float* __restrict__ RB,
      const int* __restrict__ nbrs)
{
    __shared__ float rw2s[NRBF * F];   // ch2 weights, 10 KB
    __shared__ int   sj  [CAP];
    __shared__ float senv[CAP];
    __shared__ float sux [CAP];
    __shared__ float suy [CAP];
    __shared__ float suz [CAP];
    __shared__ float srbf[CAP][NRBF];

    int f = threadIdx.x;

    // ch0/ch1 weights -> registers as packed pairs (fully unrolled accesses)
    unsigned long long rw01[NRBF];
    #pragma unroll
    for (int q = 0; q < NRBF; q++)
        rw01[q] = pk2(RW[q * F3 + f], RW[q * F3 + F + f]);
    for (int idx = f; idx < NRBF * F; idx += 128) {
        int q = idx >> 7, ff = idx & 127;
        rw2s[idx] = RW[q * F3 + 2 * F + ff];
    }
    float rb0 = RB[f], rb1 = RB[F + f], rb2 = RB[2 * F + f];

    int abase = blockIdx.x * TAM;

    for (int it = 0; it < TAM; it++) {
        int a = abase + it;
        int n = g_cnt[a];
        if (n > CAP) n = CAP;

        __syncthreads();   // prev iter smem reads done; also covers rw2s fill
        if (f < n) {
            int e = g_list[a * CAP + f];
            sj  [f] = nbrs[2 * e + 1];
            senv[f] = g_env[e];
            sux [f] = g_unit[3 * e];
            suy [f] = g_unit[3 * e + 1];
            suz [f] = g_unit[3 * e + 2];
            const float4* rp = (const float4*)(g_rbf + e * NRBF);
            float4* dst = (float4*)&srbf[f][0];
            #pragma unroll
            for (int x = 0; x < NRBF / 4; x++) dst[x] = rp[x];
        }
        __syncthreads();

        float ds = 0.0f, dv0 = 0.0f, dv1 = 0.0f, dv2 = 0.0f;
        float pj0 = 0.f, pj1 = 0.f, pj2 = 0.f, vj0 = 0.f, vj1 = 0.f, vj2 = 0.f;
        if (n > 0) {
            int j = sj[0];
            const float* pj = g_phi + j * F3;
            pj0 = pj[f]; pj1 = pj[F + f]; pj2 = pj[2 * F + f];
            const float* vj = g_v + j * F3 + f * 3;
            vj0 = vj[0]; vj1 = vj[1]; vj2 = vj[2];
        }
        for (int k = 0; k < n; k++) {
            float npj0 = 0.f, npj1 = 0.f, npj2 = 0.f, nvj0 = 0.f, nvj1 = 0.f, nvj2 = 0.f;
            if (k + 1 < n) {
                int jn = sj[k + 1];
                const float* pj = g_phi + jn * F3;
                npj0 = pj[f]; npj1 = pj[F + f]; npj2 = pj[2 * F + f];
                const float* vj = g_v + jn * F3 + f * 3;
                nvj0 = vj[0]; nvj1 = vj[1]; nvj2 = vj[2];
            }
            float env = senv[k];
            unsigned long long wA = pk2(env * rb0, env * rb1);
            unsigned long long wB = pk2(0.0f, 0.0f);
            float w2a = env * rb2, w2b = 0.0f;
            #pragma unroll
            for (int q = 0; q < NRBF; q += 2) {
                float r0 = srbf[k][q];
                float r1 = srbf[k][q + 1];
                FFMA2(wA, pk2(r0, r0), rw01[q]);
                FFMA2(wB, pk2(r1, r1), rw01[q + 1]);
                w2a = fmaf(r0, rw2s[q * F + f], w2a);
                w2b = fmaf(r1, rw2s[(q + 1) * F + f], w2b);
            }
            float2 xa = upk2(wA), xb = upk2(wB);
            float w0v = xa.x + xb.x;
            float w1v = xa.y + xb.y;
            float w2v = w2a + w2b;

            float sp0 = pj0 * w0v;
            float sp1 = pj1 * w1v;
            float sp2 = pj2 * w2v;
            ds += sp1;
            dv0 += sp2 * sux[k] + sp0 * vj0;
            dv1 += sp2 * suy[k] + sp0 * vj1;
            dv2 += sp2 * suz[k] + sp0 * vj2;

            pj0 = npj0; pj1 = npj1; pj2 = npj2;
            vj0 = nvj0; vj1 = nvj1; vj2 = nvj2;
        }
        g_ds[a * F + f] = ds;
        g_dv[a * F3 + f * 3]     = dv0;
        g_dv[a * F3 + f * 3 + 1] = dv1;
        g_dv[a * F3 + f * 3 + 2] = dv2;
    }
}

// ---------------------------------------------------------------------------
// update block (256 threads = 2 halves x 8 atoms)
// ---------------------------------------------------------------------------
__global__ void __launch_bounds__(256)
k_upd(const float* __restrict__ U,  const float* __restrict__ V,
      const float* __restrict__ W1, const float* __restrict__ B1,
      const float* __restrict__ W2, const float* __restrict__ B2)
{
    int tid  = threadIdx.x;
    int half = tid >> 7;
    int f    = tid & 127;
    int a0   = blockIdx.x * (2 * TA) + half * TA;

    __shared__ float svT[2][F][3][TA];    // 24 KB
    __shared__ float stT[2][2 * F][TA];   // 16 KB (reused as shT after W1 pass)
    float (*shT)[F][TA] = (float (*)[F][TA])&stT[0][0][0];

    float snew[TA];
    #pragma unroll
    for (int t = 0; t < TA; t++) {
        int a = a0 + t;
        float s1 = g_s[a * F + f] + g_ds[a * F + f];
        snew[t]         = s1;
        stT[half][f][t] = s1;
        #pragma unroll
        for (int d = 0; d < 3; d++)
            svT[half][f][d][t] = g_v[a * F3 + f * 3 + d] + g_dv[a * F3 + f * 3 + d];
    }
    __syncthreads();

    unsigned long long ua[3][TA / 2], wa[3][TA / 2];
    #pragma unroll
    for (int d = 0; d < 3; d++)
        #pragma unroll
        for (int p = 0; p < TA / 2; p++) { ua[d][p] = 0ULL; wa[d][p] = 0ULL; }
    for (int g = 0; g < F; g++) {
        float Ug = U[g * F + f], Vg = V[g * F + f];
        unsigned long long Up = pk2(Ug, Ug), Vp = pk2(Vg, Vg);
        #pragma unroll
        for (int d = 0; d < 3; d++) {
            const unsigned long long* row = (const unsigned long long*)&svT[half][g][d][0];
            #pragma unroll
            for (int p = 0; p < TA / 2; p++) {
                unsigned long long r = row[p];
                FFMA2(ua[d][p], r, Up);
                FFMA2(wa[d][p], r, Vp);
            }
        }
    }
    float u[TA][3], uw[TA];
    #pragma unroll
    for (int p = 0; p < TA / 2; p++) {
        float wv[2][3];
        #pragma unroll
        for (int d = 0; d < 3; d++) {
            float2 xu = upk2(ua[d][p]);
            float2 xw = upk2(wa[d][p]);
            u[2 * p][d] = xu.x; u[2 * p + 1][d] = xu.y;
            wv[0][d] = xw.x;    wv[1][d] = xw.y;
        }
        #pragma unroll
        for (int h = 0; h < 2; h++) {
            int t = 2 * p + h;
            float n2 = wv[h][0] * wv[h][0] + wv[h][1] * wv[h][1] + wv[h][2] * wv[h][2];
            stT[half][F + f][t] = sqrtf(n2 + 1e-15f);
            uw[t] = u[t][0] * wv[h][0] + u[t][1] * wv[h][1] + u[t][2] * wv[h][2];
        }
    }
    __syncthreads();

    unsigned long long hacc[TA / 2];
    {
        unsigned long long b = pk2(B1[f], B1[f]);
        #pragma unroll
        for (int p = 0; p < TA / 2; p++) hacc[p] = b;
    }
    for (int r = 0; r < 2 * F; r++) {
        float wv = W1[r * F + f];
        unsigned long long ww = pk2(wv, wv);
        const unsigned long long* row = (const unsigned long long*)&stT[half][r][0];
        #pragma unroll
        for (int p = 0; p < TA / 2; p++) FFMA2(hacc[p], row[p], ww);
    }
    __syncthreads();
    #pragma unroll
    for (int p = 0; p < TA / 2; p++) {
        float2 x = upk2(hacc[p]);
        shT[half][f][2 * p]     = silu(x.x);
        shT[half][f][2 * p + 1] = silu(x.y);
    }
    __syncthreads();

    unsigned long long p0[TA / 2], p1[TA / 2], p2[TA / 2];
    {
        unsigned long long b0 = pk2(B2[f], B2[f]);
        unsigned long long b1 = pk2(B2[F + f], B2[F + f]);
        unsigned long long b2 = pk2(B2[2 * F + f], B2[2 * F + f]);
        #pragma unroll
        for (int p = 0; p < TA / 2; p++) { p0[p] = b0; p1[p] = b1; p2[p] = b2; }
    }
    for (int g = 0; g < F; g++) {
        const float* wr = W2 + g * F3;
        unsigned long long w0 = pk2(wr[f], wr[f]);
        unsigned long long w1 = pk2(wr[F + f], wr[F + f]);
        unsigned long long w2 = pk2(wr[2 * F + f], wr[2 * F + f]);
        const unsigned long long* row = (const unsigned long long*)&shT[half][g][0];
        #pragma unroll
        for (int p = 0; p < TA / 2; p++) {
            FFMA2(p0[p], row[p], w0);
            FFMA2(p1[p], row[p], w1);
            FFMA2(p2[p], row[p], w2);
        }
    }
    #pragma unroll
    for (int p = 0; p < TA / 2; p++) {
        float2 avv = upk2(p0[p]), asv = upk2(p1[p]), ass = upk2(p2[p]);
        #pragma unroll
        for (int h = 0; h < 2; h++) {
            int t = 2 * p + h;
            int a = a0 + t;
            float a_vv = h ? avv.y : avv.x;
            float a_sv = h ? asv.y : asv.x;
            float a_ss = h ? ass.y : ass.x;
            g_s[a * F + f] = snew[t] + uw[t] * a_sv + a_ss;
            #pragma unroll
            for (int d = 0; d < 3; d++)
                g_v[a * F3 + f * 3 + d] = svT[half][f][d][t] + u[t][d] * a_vv;
        }
    }
}

// ---------------------------------------------------------------------------
// readout: 16 atoms per block, W1 amortized; 128 threads = 2 halves of 64.
// ---------------------------------------------------------------------------
#define TR 16

__global__ void k_zero_out(float* out)
{
    int t = threadIdx.x;
    if (t < NMOLS) out[t] = 0.0f;
}

__global__ void __launch_bounds__(128)
k_readout(const float* __restrict__ W1, const float* __restrict__ B1,
          const float* __restrict__ W2, const float* __restrict__ B2,
          const int* __restrict__ mol, float* __restrict__ out)
{
    int tid  = threadIdx.x;
    int half = tid >> 6;    // 0/1
    int t    = tid & 63;    // hidden unit
    int ab   = blockIdx.x * TR;

    __shared__ float ssT[F][TR];      // s transposed, 8 KB
    __shared__ float red[TR][64];     // per-atom partials, 4 KB

    for (int x = tid; x < TR * F; x += 128) {
        int aa = x >> 7, ff = x & 127;
        ssT[ff][aa] = g_s[(ab + aa) * F + ff];
    }
    __syncthreads();

    // 8 atoms per half, FFMA2 pairs
    unsigned long long acc[4];
    {
        unsigned long long b = pk2(B1[t], B1[t]);
        #pragma unroll
        for (int p = 0; p < 4; p++) acc[p] = b;
    }
    for (int g = 0; g < F; g++) {
        float w = W1[g * 64 + t];
        unsigned long long ww = pk2(w, w);
        const unsigned long long* row = (const unsigned long long*)&ssT[g][half * 8];
        #pragma unroll
        for (int p = 0; p < 4; p++) FFMA2(acc[p], row[p], ww);
    }
    float w2v = W2[t];
    #pragma unroll
    for (int p = 0; p < 4; p++) {
        float2 x = upk2(acc[p]);
        red[half * 8 + 2 * p][t]     = silu(x.x) * w2v;
        red[half * 8 + 2 * p + 1][t] = silu(x.y) * w2v;
    }
    __syncthreads();

    if (tid < TR) {
        float e = B2[0];
        #pragma unroll
        for (int q = 0; q < 64; q++) e += red[tid][q];
        atomicAdd(&out[mol[ab + tid]], e);
    }
}

// ---------------------------------------------------------------------------
// launch
// ---------------------------------------------------------------------------
extern "C" void kernel_launch(void* const* d_in, const int* in_sizes, int n_in,
                              void* d_out, int out_size)
{
    const float* xyz    = (const float*)d_in[0];
    const float* emb    = (const float*)d_in[1];
    const float* msg_w1 = (const float*)d_in[2];
    const float* msg_b1 = (const float*)d_in[3];
    const float* msg_w2 = (const float*)d_in[4];
    const float* msg_b2 = (const float*)d_in[5];
    const float* rbf_w  = (const float*)d_in[6];
    const float* rbf_b  = (const float*)d_in[7];
    const float* upd_u  = (const float*)d_in[8];
    const float* upd_v  = (const float*)d_in[9];
    const float* upd_w1 = (const float*)d_in[10];
    const float* upd_b1 = (const float*)d_in[11];
    const float* upd_w2 = (const float*)d_in[12];
    const float* upd_b2 = (const float*)d_in[13];
    const float* ro_w1  = (const float*)d_in[14];
    const float* ro_b1  = (const float*)d_in[15];
    const float* ro_w2  = (const float*)d_in[16];
    const float* ro_b2  = (const float*)d_in[17];
    const int*   z      = (const int*)d_in[18];
    const int*   nbrs   = (const int*)d_in[19];
    const int*   mol    = (const int*)d_in[20];
    float*       out    = (float*)d_out;

    int E = in_sizes[19] / 2;

    k_init <<<NATOMS, 128>>>(emb, z);
    k_edges<<<(E + 255) / 256, 256>>>(xyz, nbrs, E);

    for (int c = 0; c < NCONV; c++) {
        k_phi<<<NATOMS / (2 * TA), 256>>>(msg_w1 + c * F * F,     msg_b1 + c * F,
                                          msg_w2 + c * F * F3,    msg_b2 + c * F3);
        k_msg<<<NATOMS / TAM, 128>>>(rbf_w + c * NRBF * F3, rbf_b + c * F3, nbrs);
        k_upd<<<NATOMS / (2 * TA), 256>>>(upd_u  + c * F * F,     upd_v  + c * F * F,
                                          upd_w1 + c * 2 * F * F, upd_b1 + c * F,
                                          upd_w2 + c * F * F3,    upd_b2 + c * F3);
    }

    k_zero_out<<<1, 128>>>(out);
    k_readout <<<NATOMS / TR, 128>>>(ro_w1, ro_b1, ro_w2, ro_b2, mol, out);
}